// round 5
// baseline (speedup 1.0000x reference)
#include <cuda_runtime.h>
#include <cuda_bf16.h>

// Problem constants
#define S 8192
#define D 1024
#define E 64
#define CAP 128
#define SHIFT 4096
#define RANK_Y 8
static const long long SEC = (long long)S * E * CAP;   // 67108864

#define GEMM_BLOCKS 256          // BM=32 -> 8192/32
#define BM 32

// ---------------- scratch (device globals; no cross-call state) -------------
__device__ int   g_beste[S];
__device__ float g_gmax[S];
__device__ int   g_rank_part[RANK_Y * S];
__device__ int   g_expert_at_p[S];
__device__ int   g_token_at_p[S];
__device__ int   g_choff[S];                 // [128 chunks][64 experts] excl prefix
__device__ float g_me_part[GEMM_BLOCKS * E];
__device__ int   g_cnt_part[GEMM_BLOCKS * E];

// ---------------------------------------------------------------------------
// K1: GEMM (32 tokens x 64 experts per block) + softmax/argmax epilogue
// ---------------------------------------------------------------------------
__global__ void k1_gemm(const float* __restrict__ x,
                        const float* __restrict__ w) {
    __shared__ float As[32][BM];     // [k][m]
    __shared__ float Bs[32][64];     // [k][e]
    __shared__ float L[BM][65];      // logits, padded
    __shared__ float smax[BM], sinv[BM];
    __shared__ int   scnt[E];

    const int tid = threadIdx.x;
    const int m0  = blockIdx.x * BM;
    const int tx  = tid & 15;        // expert group (4 experts)
    const int ty  = tid >> 4;        // row group (2 rows)
    float acc[2][4];
    #pragma unroll
    for (int i = 0; i < 2; i++)
        #pragma unroll
        for (int j = 0; j < 4; j++) acc[i][j] = 0.0f;

    for (int k0 = 0; k0 < D; k0 += 32) {
        #pragma unroll
        for (int r = 0; r < 4; r++) {
            int l  = tid + r * 256;
            int mm = l & 31;
            int kk = l >> 5;
            As[kk][mm] = x[(long long)(m0 + mm) * D + k0 + kk];
        }
        #pragma unroll
        for (int r = 0; r < 8; r++) {
            int l  = tid + r * 256;
            int mm = l & 63;
            int kk = l >> 6;
            Bs[kk][mm] = w[(long long)mm * D + k0 + kk];
        }
        __syncthreads();
        #pragma unroll
        for (int kk = 0; kk < 32; kk++) {
            const float2 a = *(const float2*)(&As[kk][ty * 2]);
            const float4 b = *(const float4*)(&Bs[kk][tx * 4]);
            float av[2] = {a.x, a.y};
            float bv[4] = {b.x, b.y, b.z, b.w};
            #pragma unroll
            for (int i = 0; i < 2; i++)
                #pragma unroll
                for (int j = 0; j < 4; j++)
                    acc[i][j] += av[i] * bv[j];
        }
        __syncthreads();
    }

    #pragma unroll
    for (int i = 0; i < 2; i++)
        #pragma unroll
        for (int j = 0; j < 4; j++)
            L[ty * 2 + i][tx * 4 + j] = acc[i][j];
    if (tid < E) scnt[tid] = 0;
    __syncthreads();

    if (tid < BM) {
        const int t = tid;
        float bv = L[t][0];
        int   bi = 0;
        #pragma unroll 8
        for (int e = 1; e < E; e++) {
            float v = L[t][e];
            if (v > bv) { bv = v; bi = e; }
        }
        float s = 0.0f;
        #pragma unroll 8
        for (int e = 0; e < E; e++) s += expf(L[t][e] - bv);
        float inv = 1.0f / s;
        smax[t] = bv;
        sinv[t] = inv;
        g_beste[m0 + t] = bi;
        g_gmax[m0 + t]  = inv;               // max gate = 1/sum
        atomicAdd(&scnt[bi], 1);
    }
    __syncthreads();
    if (tid < E) {
        const int e = tid;
        float me = 0.0f;
        #pragma unroll 8
        for (int t = 0; t < BM; t++)
            me += expf(L[t][e] - smax[t]) * sinv[t];
        g_me_part[blockIdx.x * E + e]  = me;
        g_cnt_part[blockIdx.x * E + e] = scnt[e];
    }
}

// ---------------------------------------------------------------------------
// K2: rank by counting (stable argsort of -gmax), partitioned over 8 u-slices
// ---------------------------------------------------------------------------
__global__ void k_rank() {
    __shared__ float sh[1024];
    const int t = blockIdx.x * 256 + threadIdx.x;
    const int ubase = blockIdx.y * 1024;
    for (int i = threadIdx.x; i < 1024; i += 256) sh[i] = g_gmax[ubase + i];
    __syncthreads();
    const float g = g_gmax[t];
    int lo = t - ubase;
    if (lo < 0) lo = 0;
    if (lo > 1024) lo = 1024;
    int cnt = 0;
    for (int j = 0; j < lo; j++)    cnt += (sh[j] >= g);
    for (int j = lo; j < 1024; j++) cnt += (sh[j] >  g);
    g_rank_part[blockIdx.y * S + t] = cnt;
}

// ---------------------------------------------------------------------------
// K3: position (roll), scatter expert/token by position, smem histogram,
//     per-expert exclusive prefix over 128 chunks. Single block, 1024 thr.
// ---------------------------------------------------------------------------
__global__ void k_pospfx() {
    __shared__ int hist[128 * E];                 // 32 KB
    const int tid = threadIdx.x;
    for (int i = tid; i < 128 * E; i += 1024) hist[i] = 0;
    __syncthreads();
    #pragma unroll
    for (int k = 0; k < 8; k++) {
        const int t = tid + k * 1024;
        int r = 0;
        #pragma unroll
        for (int y = 0; y < RANK_Y; y++) r += g_rank_part[y * S + t];
        const int p = (r + SHIFT) & (S - 1);
        const int e = g_beste[t];
        g_expert_at_p[p] = e;
        g_token_at_p[p]  = t;
        atomicAdd(&hist[(p >> 6) * E + e], 1);
    }
    __syncthreads();
    if (tid < E) {
        int run = 0;
        #pragma unroll 1
        for (int b = 0; b < 128; b++) {
            g_choff[b * E + tid] = run;
            run += hist[b * E + tid];
        }
    }
}

// ---------------------------------------------------------------------------
// K4: per-chunk within-chunk rank + sparse scatter of combine/dispatch
// ---------------------------------------------------------------------------
__global__ void k_scatter(float* __restrict__ out) {
    __shared__ int se[64];
    const int i = threadIdx.x;
    const int p = blockIdx.x * 64 + i;
    const int e = g_expert_at_p[p];
    const int t = g_token_at_p[p];
    se[i] = e;
    __syncthreads();
    int c = 0;
    for (int j = 0; j < i; j++) c += (se[j] == e);
    const int loc = g_choff[blockIdx.x * E + e] + c;
    if (loc < CAP) {
        long long base = 1LL + ((long long)t * E + e) * CAP + loc;
        out[base]       = g_gmax[t];  // combine_weights
        out[base + SEC] = 1.0f;       // dispatch_mask
    }
}

// ---------------------------------------------------------------------------
// K5: reduce partials -> l_aux, exp_counts, unrouted_token_rate
// ---------------------------------------------------------------------------
__global__ void k_finalize(float* __restrict__ out) {
    __shared__ float red[E];
    __shared__ int   sc[E];
    const int e = threadIdx.x;
    float me = 0.0f;
    int   c  = 0;
    #pragma unroll 8
    for (int b = 0; b < GEMM_BLOCKS; b++) {
        me += g_me_part[b * E + e];
        c  += g_cnt_part[b * E + e];
    }
    const float inv = 1.0f / (float)S;
    red[e] = (me * inv) * ((float)c * inv);
    sc[e]  = c;
    out[1LL + 2LL * SEC + e] = (float)c;
    __syncthreads();
    if (e == 0) {
        float sum = 0.0f;
        int dropped = 0;
        for (int k = 0; k < E; k++) {
            sum += red[k];
            int d = sc[k] - CAP;
            if (d > 0) dropped += d;
        }
        out[0] = sum * (float)E * 0.01f;
        out[1LL + 2LL * SEC + E] = (float)dropped * inv;
    }
}

// ---------------------------------------------------------------------------
extern "C" void kernel_launch(void* const* d_in, const int* in_sizes, int n_in,
                              void* d_out, int out_size) {
    const float* x = (const float*)d_in[0];   // [S, D]
    const float* w = (const float*)d_in[1];   // [E, D]
    float* out = (float*)d_out;

    // one graph memset node zeroes the entire output (driver-optimized fill)
    cudaMemsetAsync(d_out, 0, (size_t)out_size * sizeof(float));

    k1_gemm<<<GEMM_BLOCKS, 256>>>(x, w);
    k_rank<<<dim3(S / 256, RANK_Y), 256>>>();
    k_pospfx<<<1, 1024>>>();
    k_scatter<<<S / 64, 64>>>(out);
    k_finalize<<<1, E>>>(out);
}